// round 1
// baseline (speedup 1.0000x reference)
#include <cuda_runtime.h>
#include <cuda_bf16.h>
#include <cstdint>

// Problem shape (fixed)
#define N_IMG  16
#define C_IN   3
#define H_IN   224
#define W_IN   224
#define OC     128
#define OH     222
#define OW     222
#define PLANE  (H_IN * W_IN)            // 50176
#define NPIX   (N_IMG * PLANE)          // 802816 quantized-input pixels
#define OPLANE (OH * OW)                // 49284
#define PAIRS_PER_ROW (OW / 2)          // 111
#define PAIRS_PER_IMG (OH * PAIRS_PER_ROW)  // 24642
#define NPAIRS (N_IMG * PAIRS_PER_IMG)  // 394272

// ---------------- device scratch (allocation-free rule: __device__ globals) ----
__device__ unsigned g_amax_x;   // abs-max of x, float bits (nonneg -> uint order)
__device__ unsigned g_amax_w;   // abs-max of W
__device__ unsigned g_amax_v;   // abs-max of (int accum + b_int), unscaled
__device__ int   g_xq[NPIX];              // packed char4: c0,c1,c2,0  (NHWC4)
__device__ int4  g_wq[OC * 3];            // 12 ints per oc (9 taps + 3 zero pads)
__device__ float g_bint[OC];              // bias in integer grid (round(b/(s_in*s_w)))

static __device__ __forceinline__ int pack4(int a, int b, int c, int d) {
    return (a & 0xFF) | ((b & 0xFF) << 8) | ((c & 0xFF) << 16) | ((d & 0xFF) << 24);
}

// ---------------- K0: reset scalars (graph replays must be deterministic) ------
__global__ void k_reset() {
    g_amax_x = 0u; g_amax_w = 0u; g_amax_v = 0u;
}

// ---------------- K1: abs-max of x (float4 grid) and W ------------------------
__global__ void k_absmax(const float* __restrict__ x, const float* __restrict__ w) {
    int i = blockIdx.x * blockDim.x + threadIdx.x;   // one float4 per thread
    float m = 0.0f;
    if (i < (N_IMG * C_IN * PLANE) / 4) {
        float4 v = reinterpret_cast<const float4*>(x)[i];
        m = fmaxf(fmaxf(fabsf(v.x), fabsf(v.y)), fmaxf(fabsf(v.z), fabsf(v.w)));
    }
    unsigned um = __reduce_max_sync(0xFFFFFFFFu, __float_as_uint(m));
    if ((threadIdx.x & 31) == 0 && um) atomicMax(&g_amax_x, um);

    if (blockIdx.x == 0) {
        float wm = 0.0f;
        for (int j = threadIdx.x; j < OC * C_IN * 9; j += blockDim.x)
            wm = fmaxf(wm, fabsf(w[j]));
        unsigned uw = __reduce_max_sync(0xFFFFFFFFu, __float_as_uint(wm));
        if ((threadIdx.x & 31) == 0) atomicMax(&g_amax_w, uw);
    }
}

// ---------------- K2: quantize x -> packed int8 NHWC4; W -> int4 taps; b ------
#define XBLOCKS (NPIX / 256)   // 3136, exact
__global__ void k_quant(const float* __restrict__ x, const float* __restrict__ w,
                        const float* __restrict__ b) {
    const float s_in = fmaxf(__fdiv_rn(__uint_as_float(g_amax_x), 127.0f), 1e-8f);
    if (blockIdx.x < XBLOCKS) {
        int idx = blockIdx.x * 256 + threadIdx.x;     // [0, NPIX)
        int n  = idx / PLANE;
        int hw = idx - n * PLANE;
        const float* xp = x + (size_t)n * C_IN * PLANE + hw;
        int q[3];
#pragma unroll
        for (int c = 0; c < 3; c++) {
            float t = rintf(__fdiv_rn(xp[c * PLANE], s_in));
            t = fminf(fmaxf(t, -128.0f), 127.0f);
            q[c] = (int)t;
        }
        g_xq[idx] = pack4(q[0], q[1], q[2], 0);
    } else {
        // weights + bias block
        const float s_w = fmaxf(__fdiv_rn(__uint_as_float(g_amax_w), 7.0f), 1e-8f);
        int* wq = reinterpret_cast<int*>(g_wq);
        for (int i = threadIdx.x; i < OC * 9; i += 256) {
            int oc = i / 9, l = i - oc * 9;           // l = kh*3+kw
            int q[3];
#pragma unroll
            for (int c = 0; c < 3; c++) {
                float t = rintf(__fdiv_rn(w[oc * 27 + c * 9 + l], s_w));
                t = fminf(fmaxf(t, -7.0f), 7.0f);
                q[c] = (int)t;
            }
            wq[oc * 12 + l] = pack4(q[0], q[1], q[2], 0);
        }
        for (int i = threadIdx.x; i < OC * 3; i += 256) {
            int oc = i / 3, p = i - oc * 3;
            wq[oc * 12 + 9 + p] = 0;
        }
        if (threadIdx.x < OC) {
            float s_b = s_in * s_w;
            g_bint[threadIdx.x] = rintf(__fdiv_rn(b[threadIdx.x], s_b));
        }
    }
}

// ---------------- K3/K4: conv (dp4a, exact int accum). STORE=0: max pass. -----
template <int STORE>
__global__ void __launch_bounds__(256) k_conv(float* __restrict__ out) {
    __shared__ int4  sw[OC * 3];
    __shared__ float sb[OC];
    for (int i = threadIdx.x; i < OC * 3; i += 256) sw[i] = g_wq[i];
    if (threadIdx.x < OC) sb[threadIdx.x] = g_bint[threadIdx.x];
    __syncthreads();

    int t = blockIdx.x * 256 + threadIdx.x;
    if (t >= NPAIRS) return;

    int n   = t / PAIRS_PER_IMG;
    int r   = t - n * PAIRS_PER_IMG;
    int oh  = r / PAIRS_PER_ROW;
    int ow0 = (r - oh * PAIRS_PER_ROW) * 2;

    // 3 rows x 4 cols of packed input words (covers both ow0 and ow0+1)
    const int* xp = g_xq + (n * H_IN + oh) * W_IN + ow0;
    int a00 = __ldg(xp + 0),            a01 = __ldg(xp + 1),
        a02 = __ldg(xp + 2),            a03 = __ldg(xp + 3);
    int a10 = __ldg(xp + W_IN + 0),     a11 = __ldg(xp + W_IN + 1),
        a12 = __ldg(xp + W_IN + 2),     a13 = __ldg(xp + W_IN + 3);
    int a20 = __ldg(xp + 2 * W_IN + 0), a21 = __ldg(xp + 2 * W_IN + 1),
        a22 = __ldg(xp + 2 * W_IN + 2), a23 = __ldg(xp + 2 * W_IN + 3);

    float s_b = 0.f, s_out = 0.f, rinv = 0.f;
    float* obase = nullptr;
    if (STORE) {
        const float s_in = fmaxf(__fdiv_rn(__uint_as_float(g_amax_x), 127.0f), 1e-8f);
        const float s_w  = fmaxf(__fdiv_rn(__uint_as_float(g_amax_w), 7.0f), 1e-8f);
        s_b  = s_in * s_w;
        float maxy = s_b * __uint_as_float(g_amax_v);
        s_out = fmaxf(__fdiv_rn(maxy, 127.0f), 1e-8f);
        rinv  = __fdiv_rn(1.0f, s_out);
        obase = out + (size_t)n * OC * OPLANE + (size_t)oh * OW + ow0;
    }

    float m = 0.0f;
#pragma unroll 4
    for (int oc = 0; oc < OC; oc++) {
        int4 w0 = sw[oc * 3], w1 = sw[oc * 3 + 1], w2 = sw[oc * 3 + 2];
        int acc0 = __dp4a(a00, w0.x, __dp4a(a01, w0.y, __dp4a(a02, w0.z,
                   __dp4a(a10, w0.w, __dp4a(a11, w1.x, __dp4a(a12, w1.y,
                   __dp4a(a20, w1.z, __dp4a(a21, w1.w, __dp4a(a22, w2.x, 0)))))))));
        int acc1 = __dp4a(a01, w0.x, __dp4a(a02, w0.y, __dp4a(a03, w0.z,
                   __dp4a(a11, w0.w, __dp4a(a12, w1.x, __dp4a(a13, w1.y,
                   __dp4a(a21, w1.z, __dp4a(a22, w1.w, __dp4a(a23, w2.x, 0)))))))));
        float v0 = (float)acc0 + sb[oc];
        float v1 = (float)acc1 + sb[oc];
        if (STORE) {
            float q0 = fminf(fmaxf(rintf(s_b * v0 * rinv), -128.0f), 127.0f) * s_out;
            float q1 = fminf(fmaxf(rintf(s_b * v1 * rinv), -128.0f), 127.0f) * s_out;
            *reinterpret_cast<float2*>(obase + (size_t)oc * OPLANE) = make_float2(q0, q1);
        } else {
            m = fmaxf(m, fmaxf(fabsf(v0), fabsf(v1)));
        }
    }
    if (!STORE) {
        unsigned um = __reduce_max_sync(0xFFFFFFFFu, __float_as_uint(m));
        if ((threadIdx.x & 31) == 0) atomicMax(&g_amax_v, um);
    }
}

// ---------------- launcher -----------------------------------------------------
extern "C" void kernel_launch(void* const* d_in, const int* in_sizes, int n_in,
                              void* d_out, int out_size) {
    // identify inputs by element count (robust to metadata order)
    const float *x = nullptr, *w = nullptr, *b = nullptr;
    for (int i = 0; i < n_in; i++) {
        if (in_sizes[i] == N_IMG * C_IN * PLANE)      x = (const float*)d_in[i];
        else if (in_sizes[i] == OC * C_IN * 9)        w = (const float*)d_in[i];
        else if (in_sizes[i] == OC)                   b = (const float*)d_in[i];
    }
    float* out = (float*)d_out;

    k_reset<<<1, 32>>>();

    int n4 = (N_IMG * C_IN * PLANE) / 4;              // 602112
    k_absmax<<<(n4 + 255) / 256, 256>>>(x, w);

    k_quant<<<XBLOCKS + 1, 256>>>(x, w, b);

    int cblocks = (NPAIRS + 255) / 256;               // 1541
    k_conv<0><<<cblocks, 256>>>(out);
    k_conv<1><<<cblocks, 256>>>(out);
}

// round 2
// speedup vs baseline: 1.0108x; 1.0108x over previous
#include <cuda_runtime.h>
#include <cuda_bf16.h>
#include <cstdint>

// Problem shape (fixed)
#define N_IMG  16
#define C_IN   3
#define H_IN   224
#define W_IN   224
#define OC     128
#define OH     222
#define OW     222
#define PLANE  (H_IN * W_IN)            // 50176
#define NPIX   (N_IMG * PLANE)          // 802816 quantized-input pixels
#define OPLANE (OH * OW)                // 49284
#define TILES_PER_ROW (OW / 2)          // 111
#define TILES_PER_IMG ((OH / 2) * TILES_PER_ROW)  // 12321
#define NTILES (N_IMG * TILES_PER_IMG)  // 197136

// ---------------- device scratch (allocation-free rule: __device__ globals) ----
__device__ unsigned g_amax_x;   // abs-max of x, float bits
__device__ unsigned g_amax_w;   // abs-max of W
__device__ int      g_amax_v;   // abs-max of integer (acc + bias_int), nonneg
__device__ int   g_xq[NPIX];              // packed char4: c0,c1,c2,0  (NHWC4)
__device__ int4  g_wq[OC * 3];            // 12 ints per oc (9 taps + 3 zero pads)
__device__ int   g_bi[OC];                // bias on integer grid: round(b/(s_in*s_w))

static __device__ __forceinline__ int pack4(int a, int b, int c, int d) {
    return (a & 0xFF) | ((b & 0xFF) << 8) | ((c & 0xFF) << 16) | ((d & 0xFF) << 24);
}

// ---------------- K0: reset scalars ------------------------------------------
__global__ void k_reset() {
    g_amax_x = 0u; g_amax_w = 0u; g_amax_v = 0;
}

// ---------------- K1: abs-max of x (float4 grid) and W ------------------------
__global__ void k_absmax(const float* __restrict__ x, const float* __restrict__ w) {
    int i = blockIdx.x * blockDim.x + threadIdx.x;   // one float4 per thread
    float m = 0.0f;
    if (i < (N_IMG * C_IN * PLANE) / 4) {
        float4 v = reinterpret_cast<const float4*>(x)[i];
        m = fmaxf(fmaxf(fabsf(v.x), fabsf(v.y)), fmaxf(fabsf(v.z), fabsf(v.w)));
    }
    unsigned um = __reduce_max_sync(0xFFFFFFFFu, __float_as_uint(m));
    if ((threadIdx.x & 31) == 0 && um) atomicMax(&g_amax_x, um);

    if (blockIdx.x == 0) {
        float wm = 0.0f;
        for (int j = threadIdx.x; j < OC * C_IN * 9; j += blockDim.x)
            wm = fmaxf(wm, fabsf(w[j]));
        unsigned uw = __reduce_max_sync(0xFFFFFFFFu, __float_as_uint(wm));
        if ((threadIdx.x & 31) == 0) atomicMax(&g_amax_w, uw);
    }
}

// ---------------- K2: quantize x -> packed int8 NHWC4; W -> int4 taps; bias ----
#define XBLOCKS (NPIX / 256)   // 3136, exact
__global__ void k_quant(const float* __restrict__ x, const float* __restrict__ w,
                        const float* __restrict__ b) {
    const float s_in = fmaxf(__fdiv_rn(__uint_as_float(g_amax_x), 127.0f), 1e-8f);
    if (blockIdx.x < XBLOCKS) {
        int idx = blockIdx.x * 256 + threadIdx.x;     // [0, NPIX)
        int n  = idx / PLANE;
        int hw = idx - n * PLANE;
        const float* xp = x + (size_t)n * C_IN * PLANE + hw;
        int q[3];
#pragma unroll
        for (int c = 0; c < 3; c++) {
            float t = rintf(__fdiv_rn(xp[c * PLANE], s_in));
            t = fminf(fmaxf(t, -128.0f), 127.0f);
            q[c] = (int)t;
        }
        g_xq[idx] = pack4(q[0], q[1], q[2], 0);
    } else {
        const float s_w = fmaxf(__fdiv_rn(__uint_as_float(g_amax_w), 7.0f), 1e-8f);
        int* wq = reinterpret_cast<int*>(g_wq);
        for (int i = threadIdx.x; i < OC * 9; i += 256) {
            int oc = i / 9, l = i - oc * 9;           // l = kh*3+kw
            int q[3];
#pragma unroll
            for (int c = 0; c < 3; c++) {
                float t = rintf(__fdiv_rn(w[oc * 27 + c * 9 + l], s_w));
                t = fminf(fmaxf(t, -7.0f), 7.0f);
                q[c] = (int)t;
            }
            wq[oc * 12 + l] = pack4(q[0], q[1], q[2], 0);
        }
        for (int i = threadIdx.x; i < OC * 3; i += 256) {
            int oc = i / 3, p = i - oc * 3;
            wq[oc * 12 + 9 + p] = 0;
        }
        if (threadIdx.x < OC) {
            float s_b = s_in * s_w;
            float t = rintf(__fdiv_rn(b[threadIdx.x], s_b));
            t = fminf(fmaxf(t, -2.0e9f), 2.0e9f);
            g_bi[threadIdx.x] = (int)t;
        }
    }
}

// 9-tap dp4a chain, accumulator initialized with integer bias
static __device__ __forceinline__ int dp9(int x0, int x1, int x2,
                                          int x3, int x4, int x5,
                                          int x6, int x7, int x8,
                                          int4 w0, int4 w1, int w2x, int init) {
    int s = __dp4a(x0, w0.x, init);
    s = __dp4a(x1, w0.y, s); s = __dp4a(x2, w0.z, s);
    s = __dp4a(x3, w0.w, s); s = __dp4a(x4, w1.x, s); s = __dp4a(x5, w1.y, s);
    s = __dp4a(x6, w1.z, s); s = __dp4a(x7, w1.w, s); s = __dp4a(x8, w2x, s);
    return s;
}

// ---------------- K3/K4: conv, 2x2 output tile per thread. STORE=0: max pass. --
template <int STORE>
__global__ void __launch_bounds__(256) k_conv(float* __restrict__ out) {
    __shared__ int4 sw[OC * 3];
    __shared__ int  sbi[OC];
    for (int i = threadIdx.x; i < OC * 3; i += 256) sw[i] = g_wq[i];
    if (threadIdx.x < OC) sbi[threadIdx.x] = g_bi[threadIdx.x];
    __syncthreads();

    int t = blockIdx.x * 256 + threadIdx.x;
    if (t >= NTILES) return;

    int n   = t / TILES_PER_IMG;
    int r   = t - n * TILES_PER_IMG;
    int th  = r / TILES_PER_ROW;
    int tw  = r - th * TILES_PER_ROW;
    int oh  = th * 2;
    int ow0 = tw * 2;

    // 4 rows x 4 cols of packed input words (covers the 2x2 output tile)
    const int* xp = g_xq + (n * H_IN + oh) * W_IN + ow0;
    int a00 = __ldg(xp + 0),            a01 = __ldg(xp + 1),
        a02 = __ldg(xp + 2),            a03 = __ldg(xp + 3);
    int a10 = __ldg(xp + W_IN + 0),     a11 = __ldg(xp + W_IN + 1),
        a12 = __ldg(xp + W_IN + 2),     a13 = __ldg(xp + W_IN + 3);
    int a20 = __ldg(xp + 2 * W_IN + 0), a21 = __ldg(xp + 2 * W_IN + 1),
        a22 = __ldg(xp + 2 * W_IN + 2), a23 = __ldg(xp + 2 * W_IN + 3);
    int a30 = __ldg(xp + 3 * W_IN + 0), a31 = __ldg(xp + 3 * W_IN + 1),
        a32 = __ldg(xp + 3 * W_IN + 2), a33 = __ldg(xp + 3 * W_IN + 3);

    float kf = 0.f, s_out = 0.f;
    float* obase = nullptr;
    if (STORE) {
        const float s_in = fmaxf(__fdiv_rn(__uint_as_float(g_amax_x), 127.0f), 1e-8f);
        const float s_w  = fmaxf(__fdiv_rn(__uint_as_float(g_amax_w), 7.0f), 1e-8f);
        float s_b = s_in * s_w;
        float maxy = s_b * (float)g_amax_v;
        s_out = fmaxf(__fdiv_rn(maxy, 127.0f), 1e-8f);
        kf = __fdiv_rn(s_b, s_out);
        obase = out + (size_t)n * OC * OPLANE + (size_t)oh * OW + ow0;
    }

    int m = 0;
#pragma unroll 8
    for (int oc = 0; oc < OC; oc++) {
        int4 w0 = sw[oc * 3], w1 = sw[oc * 3 + 1];
        int  w2x = sw[oc * 3 + 2].x;
        int  bi = sbi[oc];
        int acc00 = dp9(a00, a01, a02, a10, a11, a12, a20, a21, a22, w0, w1, w2x, bi);
        int acc01 = dp9(a01, a02, a03, a11, a12, a13, a21, a22, a23, w0, w1, w2x, bi);
        int acc10 = dp9(a10, a11, a12, a20, a21, a22, a30, a31, a32, w0, w1, w2x, bi);
        int acc11 = dp9(a11, a12, a13, a21, a22, a23, a31, a32, a33, w0, w1, w2x, bi);
        if (STORE) {
            float q00 = fminf(fmaxf(rintf((float)acc00 * kf), -128.0f), 127.0f) * s_out;
            float q01 = fminf(fmaxf(rintf((float)acc01 * kf), -128.0f), 127.0f) * s_out;
            float q10 = fminf(fmaxf(rintf((float)acc10 * kf), -128.0f), 127.0f) * s_out;
            float q11 = fminf(fmaxf(rintf((float)acc11 * kf), -128.0f), 127.0f) * s_out;
            float* op = obase + (size_t)oc * OPLANE;
            *reinterpret_cast<float2*>(op)      = make_float2(q00, q01);
            *reinterpret_cast<float2*>(op + OW) = make_float2(q10, q11);
        } else {
            int m0 = max(abs(acc00), abs(acc01));
            int m1 = max(abs(acc10), abs(acc11));
            m = max(m, max(m0, m1));
        }
    }
    if (!STORE) {
        m = __reduce_max_sync(0xFFFFFFFFu, m);
        if ((threadIdx.x & 31) == 0) atomicMax(&g_amax_v, m);
    }
}

// ---------------- launcher -----------------------------------------------------
extern "C" void kernel_launch(void* const* d_in, const int* in_sizes, int n_in,
                              void* d_out, int out_size) {
    const float *x = nullptr, *w = nullptr, *b = nullptr;
    for (int i = 0; i < n_in; i++) {
        if (in_sizes[i] == N_IMG * C_IN * PLANE)      x = (const float*)d_in[i];
        else if (in_sizes[i] == OC * C_IN * 9)        w = (const float*)d_in[i];
        else if (in_sizes[i] == OC)                   b = (const float*)d_in[i];
    }
    float* out = (float*)d_out;

    k_reset<<<1, 32>>>();

    int n4 = (N_IMG * C_IN * PLANE) / 4;              // 602112
    k_absmax<<<(n4 + 255) / 256, 256>>>(x, w);

    k_quant<<<XBLOCKS + 1, 256>>>(x, w, b);

    int cblocks = (NTILES + 255) / 256;               // 771
    k_conv<0><<<cblocks, 256>>>(out);
    k_conv<1><<<cblocks, 256>>>(out);
}

// round 3
// speedup vs baseline: 1.0139x; 1.0031x over previous
#include <cuda_runtime.h>
#include <cuda_bf16.h>
#include <cstdint>

// Problem shape (fixed)
#define N_IMG  16
#define C_IN   3
#define H_IN   224
#define W_IN   224
#define OC     128
#define OH     222
#define OW     222
#define PLANE  (H_IN * W_IN)            // 50176
#define NPIX   (N_IMG * PLANE)          // 802816
#define OPLANE (OH * OW)                // 49284 (divisible by 4)
#define NPOS   (N_IMG * OPLANE)         // 788544 output positions
#define NT4    (NPOS / 4)               // 197136 conv threads (4 positions each)

// ---------------- device scratch ------------------------------------------------
__device__ unsigned g_amax_x;
__device__ unsigned g_amax_w;
__device__ int      g_amax_v;
__device__ int   g_xq[NPIX];        // packed char4 (c0,c1,c2,0) per pixel
__device__ int4  g_im[NPOS * 2];    // dense im2col: 27 bytes + pad per position (32B)
__device__ int4  g_wqp[OC * 2];     // per oc: 7 packed weight words + bias int (word 7)

static __device__ __forceinline__ int pack4(int a, int b, int c, int d) {
    return (a & 0xFF) | ((b & 0xFF) << 8) | ((c & 0xFF) << 16) | ((d & 0xFF) << 24);
}

// ---------------- K0: reset scalars ---------------------------------------------
__global__ void k_reset() {
    g_amax_x = 0u; g_amax_w = 0u; g_amax_v = 0;
}

// ---------------- K1: abs-max of x (float4 grid) and W --------------------------
__global__ void k_absmax(const float* __restrict__ x, const float* __restrict__ w) {
    int i = blockIdx.x * blockDim.x + threadIdx.x;
    float m = 0.0f;
    if (i < (N_IMG * C_IN * PLANE) / 4) {
        float4 v = reinterpret_cast<const float4*>(x)[i];
        m = fmaxf(fmaxf(fabsf(v.x), fabsf(v.y)), fmaxf(fabsf(v.z), fabsf(v.w)));
    }
    unsigned um = __reduce_max_sync(0xFFFFFFFFu, __float_as_uint(m));
    if ((threadIdx.x & 31) == 0 && um) atomicMax(&g_amax_x, um);

    if (blockIdx.x == 0) {
        float wm = 0.0f;
        for (int j = threadIdx.x; j < OC * C_IN * 9; j += blockDim.x)
            wm = fmaxf(wm, fabsf(w[j]));
        unsigned uw = __reduce_max_sync(0xFFFFFFFFu, __float_as_uint(wm));
        if ((threadIdx.x & 31) == 0) atomicMax(&g_amax_w, uw);
    }
}

// ---------------- K2: quantize x -> char4 words; W -> dense 7-word records ------
// byte order for im2col/weights: index i = tap*3 + channel, i in [0,27), byte 27 = 0
#define XBLOCKS (NPIX / 256)   // 3136, exact
__global__ void k_quant(const float* __restrict__ x, const float* __restrict__ w,
                        const float* __restrict__ b) {
    const float s_in = fmaxf(__fdiv_rn(__uint_as_float(g_amax_x), 127.0f), 1e-8f);
    if (blockIdx.x < XBLOCKS) {
        int idx = blockIdx.x * 256 + threadIdx.x;
        int n  = idx / PLANE;
        int hw = idx - n * PLANE;
        const float* xp = x + (size_t)n * C_IN * PLANE + hw;
        int q[3];
#pragma unroll
        for (int c = 0; c < 3; c++) {
            float t = rintf(__fdiv_rn(xp[c * PLANE], s_in));
            t = fminf(fmaxf(t, -128.0f), 127.0f);
            q[c] = (int)t;
        }
        g_xq[idx] = pack4(q[0], q[1], q[2], 0);
    } else if (threadIdx.x < OC) {
        const float s_w = fmaxf(__fdiv_rn(__uint_as_float(g_amax_w), 7.0f), 1e-8f);
        int oc = threadIdx.x;
        int m[28];
#pragma unroll
        for (int i = 0; i < 27; i++) {
            int t = i / 3, c = i - t * 3;              // tap-major, channel-minor
            float v = rintf(__fdiv_rn(w[oc * 27 + c * 9 + t], s_w));
            v = fminf(fmaxf(v, -7.0f), 7.0f);
            m[i] = (int)v;
        }
        m[27] = 0;
        int wd[8];
#pragma unroll
        for (int j = 0; j < 7; j++)
            wd[j] = pack4(m[4 * j], m[4 * j + 1], m[4 * j + 2], m[4 * j + 3]);
        float s_b = s_in * s_w;
        float bt = rintf(__fdiv_rn(b[oc], s_b));
        bt = fminf(fmaxf(bt, -2.0e9f), 2.0e9f);
        wd[7] = (int)bt;                               // bias int rides in word 7
        g_wqp[oc * 2]     = make_int4(wd[0], wd[1], wd[2], wd[3]);
        g_wqp[oc * 2 + 1] = make_int4(wd[4], wd[5], wd[6], wd[7]);
    }
}

// ---------------- K3: im2col repack (9 sparse words -> 7 dense words) -----------
__global__ void k_im2col() {
    int p = blockIdx.x * 256 + threadIdx.x;
    if (p >= NPOS) return;
    int n  = p / OPLANE;
    int r  = p - n * OPLANE;
    int oh = r / OW;
    int ow = r - oh * OW;
    const int* xp = g_xq + (n * H_IN + oh) * W_IN + ow;
    int t0 = xp[0],            t1 = xp[1],            t2 = xp[2];
    int t3 = xp[W_IN],         t4 = xp[W_IN + 1],     t5 = xp[W_IN + 2];
    int t6 = xp[2 * W_IN],     t7 = xp[2 * W_IN + 1], t8 = xp[2 * W_IN + 2];
    int4 lo, hi;
    lo.x = __byte_perm(t0, t1, 0x4210);   // t0c0 t0c1 t0c2 t1c0
    lo.y = __byte_perm(t1, t2, 0x5421);   // t1c1 t1c2 t2c0 t2c1
    lo.z = __byte_perm(t2, t3, 0x6542);   // t2c2 t3c0 t3c1 t3c2
    lo.w = __byte_perm(t4, t5, 0x4210);   // t4c0 t4c1 t4c2 t5c0
    hi.x = __byte_perm(t5, t6, 0x5421);   // t5c1 t5c2 t6c0 t6c1
    hi.y = __byte_perm(t6, t7, 0x6542);   // t6c2 t7c0 t7c1 t7c2
    hi.z = __byte_perm(t8, 0,  0x4210);   // t8c0 t8c1 t8c2 0
    hi.w = 0;
    g_im[p * 2]     = lo;
    g_im[p * 2 + 1] = hi;
}

// 7-word dp4a dot, accumulator initialized with integer bias
static __device__ __forceinline__ int dot7(int4 xa, int4 xb, int4 wa, int4 wb, int bi) {
    int s = __dp4a(xa.x, wa.x, bi);
    s = __dp4a(xa.y, wa.y, s); s = __dp4a(xa.z, wa.z, s); s = __dp4a(xa.w, wa.w, s);
    s = __dp4a(xb.x, wb.x, s); s = __dp4a(xb.y, wb.y, s); s = __dp4a(xb.z, wb.z, s);
    return s;
}

// ---------------- K4/K5: conv over dense im2col. STORE=0: max pass ---------------
template <int STORE>
__global__ void __launch_bounds__(256) k_conv(float* __restrict__ out) {
    __shared__ int4 sw[OC * 2];
    for (int i = threadIdx.x; i < OC * 2; i += 256) sw[i] = g_wqp[i];
    __syncthreads();

    int t = blockIdx.x * 256 + threadIdx.x;
    if (t >= NT4) return;
    int p0 = t * 4;                       // 4 consecutive positions, same n-plane

    const int4* ip = g_im + (size_t)p0 * 2;
    int4 x0a = ip[0], x0b = ip[1];
    int4 x1a = ip[2], x1b = ip[3];
    int4 x2a = ip[4], x2b = ip[5];
    int4 x3a = ip[6], x3b = ip[7];

    float kf = 0.f, s_out = 0.f;
    float* obase = nullptr;
    if (STORE) {
        const float s_in = fmaxf(__fdiv_rn(__uint_as_float(g_amax_x), 127.0f), 1e-8f);
        const float s_w  = fmaxf(__fdiv_rn(__uint_as_float(g_amax_w), 7.0f), 1e-8f);
        float s_b  = s_in * s_w;
        float maxy = s_b * (float)g_amax_v;
        s_out = fmaxf(__fdiv_rn(maxy, 127.0f), 1e-8f);
        kf = __fdiv_rn(s_b, s_out);
        int n = p0 / OPLANE, rem = p0 - n * OPLANE;   // no plane wrap: 4 | OPLANE
        obase = out + (size_t)n * OC * OPLANE + rem;
    }

    int m = 0;
#pragma unroll 4
    for (int oc = 0; oc < OC; oc++) {
        int4 wa = sw[oc * 2], wb = sw[oc * 2 + 1];
        int bi = wb.w;
        int a0 = dot7(x0a, x0b, wa, wb, bi);
        int a1 = dot7(x1a, x1b, wa, wb, bi);
        int a2 = dot7(x2a, x2b, wa, wb, bi);
        int a3 = dot7(x3a, x3b, wa, wb, bi);
        if (STORE) {
            // clamp is provably inactive: |acc*kf| <= 127 by construction of s_out
            float4 q;
            q.x = rintf((float)a0 * kf) * s_out;
            q.y = rintf((float)a1 * kf) * s_out;
            q.z = rintf((float)a2 * kf) * s_out;
            q.w = rintf((float)a3 * kf) * s_out;
            *reinterpret_cast<float4*>(obase + (size_t)oc * OPLANE) = q;
        } else {
            m = max(m, max(max(abs(a0), abs(a1)), max(abs(a2), abs(a3))));
        }
    }
    if (!STORE) {
        m = __reduce_max_sync(0xFFFFFFFFu, m);
        if ((threadIdx.x & 31) == 0) atomicMax(&g_amax_v, m);
    }
}

// ---------------- launcher --------------------------------------------------------
extern "C" void kernel_launch(void* const* d_in, const int* in_sizes, int n_in,
                              void* d_out, int out_size) {
    const float *x = nullptr, *w = nullptr, *b = nullptr;
    for (int i = 0; i < n_in; i++) {
        if (in_sizes[i] == N_IMG * C_IN * PLANE)      x = (const float*)d_in[i];
        else if (in_sizes[i] == OC * C_IN * 9)        w = (const float*)d_in[i];
        else if (in_sizes[i] == OC)                   b = (const float*)d_in[i];
    }
    float* out = (float*)d_out;

    k_reset<<<1, 32>>>();

    int n4 = (N_IMG * C_IN * PLANE) / 4;
    k_absmax<<<(n4 + 255) / 256, 256>>>(x, w);

    k_quant<<<XBLOCKS + 1, 256>>>(x, w, b);

    k_im2col<<<(NPOS + 255) / 256, 256>>>();

    int cblocks = (NT4 + 255) / 256;      // 771
    k_conv<0><<<cblocks, 256>>>(out);
    k_conv<1><<<cblocks, 256>>>(out);
}